// round 1
// baseline (speedup 1.0000x reference)
#include <cuda_runtime.h>
#include <math.h>

// Problem constants
#define B_   16
#define S_   2048
#define DIN  512
#define DH   1024
#define DH2  512     // D_H/2
#define DOUT 10
#define M_   (B_ * S_)   // 32768 rows for MLP GEMMs

// Scratch (device globals: allocation-free per harness rules)
__device__ float g_h1[(size_t)M_ * (2 * DIN)];      // 128 MB  relu(x@W1+b1)
__device__ float g_h [(size_t)M_ * DH];             // 128 MB  relu(h1@W2+b2)
__device__ float g_attn[(size_t)B_ * S_ * S_];      // 256 MB  scores -> attn (in place)
__device__ float g_ctx[(size_t)M_ * DH];            // 128 MB  attn @ h
__device__ float g_o  [(size_t)M_ * DH2];           //  64 MB  relu(ctx@W3+b3)

// ---------------------------------------------------------------------------
// Generic fp32 tiled GEMM: C = act(A[M,K] @ W[K,N] + bias), 64x64x16 tiles,
// 256 threads, 4x4 micro-tile per thread. M,N multiples of 64; K multiple of 16.
// ---------------------------------------------------------------------------
template<bool RELU>
__global__ void gemm_nn(const float* __restrict__ A, const float* __restrict__ W,
                        const float* __restrict__ bias, float* __restrict__ C,
                        int M, int N, int K)
{
    const int BM = 64, BN = 64, BK = 16;
    __shared__ float As[BK][BM];
    __shared__ float Bs[BK][BN];

    const int tid = threadIdx.x;            // 0..255
    const int tx = tid & 15, ty = tid >> 4; // 16x16
    const int row0 = blockIdx.y * BM;
    const int col0 = blockIdx.x * BN;

    const int a_row  = tid >> 2;            // 0..63
    const int a_col4 = (tid & 3) * 4;       // 0,4,8,12
    const int b_row  = tid >> 4;            // 0..15
    const int b_col4 = (tid & 15) * 4;      // 0..60

    float acc[4][4] = {};

    for (int k0 = 0; k0 < K; k0 += BK) {
        float4 av = *(const float4*)(A + (size_t)(row0 + a_row) * K + k0 + a_col4);
        As[a_col4 + 0][a_row] = av.x;
        As[a_col4 + 1][a_row] = av.y;
        As[a_col4 + 2][a_row] = av.z;
        As[a_col4 + 3][a_row] = av.w;
        *(float4*)&Bs[b_row][b_col4] =
            *(const float4*)(W + (size_t)(k0 + b_row) * N + col0 + b_col4);
        __syncthreads();

        #pragma unroll
        for (int kk = 0; kk < BK; kk++) {
            float4 a4 = *(const float4*)&As[kk][ty * 4];
            float4 b4 = *(const float4*)&Bs[kk][tx * 4];
            float ar[4] = {a4.x, a4.y, a4.z, a4.w};
            float br[4] = {b4.x, b4.y, b4.z, b4.w};
            #pragma unroll
            for (int i = 0; i < 4; i++)
                #pragma unroll
                for (int j = 0; j < 4; j++)
                    acc[i][j] = fmaf(ar[i], br[j], acc[i][j]);
        }
        __syncthreads();
    }

    #pragma unroll
    for (int i = 0; i < 4; i++) {
        int r = row0 + ty * 4 + i;
        #pragma unroll
        for (int j = 0; j < 4; j++) {
            int c = col0 + tx * 4 + j;
            float v = acc[i][j] + (bias ? bias[c] : 0.0f);
            if (RELU) v = fmaxf(v, 0.0f);
            C[(size_t)r * N + c] = v;
        }
    }
}

// ---------------------------------------------------------------------------
// Causal scores: S[b,i,j] = sum_k H[b,i,k]*H[b,j,k] for tile blocks touching
// the lower triangle. Blocks fully above the diagonal are skipped (softmax
// never reads them).
// ---------------------------------------------------------------------------
__global__ void scores_kernel(const float* __restrict__ H, float* __restrict__ Sc)
{
    const int BM = 64, BN = 64, BK = 16;
    const int bj = blockIdx.x, bi = blockIdx.y, bb = blockIdx.z;
    if (bj * BN > bi * BM + (BM - 1)) return;   // uniform per block

    const float* Hb = H  + (size_t)bb * S_ * DH;
    float*       Sb = Sc + (size_t)bb * S_ * S_;

    __shared__ float As[BK][BM];
    __shared__ float Bs[BK][BN];

    const int tid = threadIdx.x;
    const int tx = tid & 15, ty = tid >> 4;
    const int i0 = bi * BM, j0 = bj * BN;
    const int a_row  = tid >> 2;
    const int a_col4 = (tid & 3) * 4;

    float acc[4][4] = {};

    for (int k0 = 0; k0 < DH; k0 += BK) {
        float4 av = *(const float4*)(Hb + (size_t)(i0 + a_row) * DH + k0 + a_col4);
        As[a_col4 + 0][a_row] = av.x;
        As[a_col4 + 1][a_row] = av.y;
        As[a_col4 + 2][a_row] = av.z;
        As[a_col4 + 3][a_row] = av.w;
        float4 bv = *(const float4*)(Hb + (size_t)(j0 + a_row) * DH + k0 + a_col4);
        Bs[a_col4 + 0][a_row] = bv.x;
        Bs[a_col4 + 1][a_row] = bv.y;
        Bs[a_col4 + 2][a_row] = bv.z;
        Bs[a_col4 + 3][a_row] = bv.w;
        __syncthreads();

        #pragma unroll
        for (int kk = 0; kk < BK; kk++) {
            float4 a4 = *(const float4*)&As[kk][ty * 4];
            float4 b4 = *(const float4*)&Bs[kk][tx * 4];
            float ar[4] = {a4.x, a4.y, a4.z, a4.w};
            float br[4] = {b4.x, b4.y, b4.z, b4.w};
            #pragma unroll
            for (int i = 0; i < 4; i++)
                #pragma unroll
                for (int j = 0; j < 4; j++)
                    acc[i][j] = fmaf(ar[i], br[j], acc[i][j]);
        }
        __syncthreads();
    }

    #pragma unroll
    for (int i = 0; i < 4; i++) {
        int r = i0 + ty * 4 + i;
        #pragma unroll
        for (int j = 0; j < 4; j++)
            Sb[(size_t)r * S_ + (j0 + tx * 4 + j)] = acc[i][j];
    }
}

// ---------------------------------------------------------------------------
// Row-wise causal softmax (in place). Row i: softmax over j in [0,i];
// writes 0 for j > i so the ctx GEMM can run dense with a K cutoff.
// ---------------------------------------------------------------------------
__global__ void softmax_causal(float* __restrict__ Sc)
{
    const int row = blockIdx.x;
    const int bb  = blockIdx.y;
    float* r = Sc + (size_t)bb * S_ * S_ + (size_t)row * S_;
    const int n = row + 1;
    const int tid = threadIdx.x;

    __shared__ float red[256];

    float m = -INFINITY;
    for (int j = tid; j < n; j += 256) m = fmaxf(m, r[j]);
    red[tid] = m; __syncthreads();
    for (int s = 128; s > 0; s >>= 1) {
        if (tid < s) red[tid] = fmaxf(red[tid], red[tid + s]);
        __syncthreads();
    }
    m = red[0];
    __syncthreads();

    float sum = 0.0f;
    for (int j = tid; j < n; j += 256) sum += __expf(r[j] - m);
    red[tid] = sum; __syncthreads();
    for (int s = 128; s > 0; s >>= 1) {
        if (tid < s) red[tid] += red[tid + s];
        __syncthreads();
    }
    const float inv = 1.0f / red[0];

    for (int j = tid; j < S_; j += 256)
        r[j] = (j < n) ? __expf(r[j] - m) * inv : 0.0f;
}

// ---------------------------------------------------------------------------
// ctx = attn @ H per batch, with per-block K cutoff (attn is zero above diag).
// ---------------------------------------------------------------------------
__global__ void ctx_kernel(const float* __restrict__ Attn, const float* __restrict__ H,
                           float* __restrict__ C)
{
    const int BM = 64, BN = 64, BK = 16;
    const int bb = blockIdx.z;
    const float* Ab = Attn + (size_t)bb * S_ * S_;
    const float* Hb = H    + (size_t)bb * S_ * DH;
    float*       Cb = C    + (size_t)bb * S_ * DH;

    __shared__ float As[BK][BM];
    __shared__ float Bs[BK][BN];

    const int tid = threadIdx.x;
    const int tx = tid & 15, ty = tid >> 4;
    const int row0 = blockIdx.y * BM;
    const int col0 = blockIdx.x * BN;
    const int kmax = row0 + BM;             // attn[i,k]=0 for k>i

    const int a_row  = tid >> 2;
    const int a_col4 = (tid & 3) * 4;
    const int b_row  = tid >> 4;
    const int b_col4 = (tid & 15) * 4;

    float acc[4][4] = {};

    for (int k0 = 0; k0 < kmax; k0 += BK) {
        float4 av = *(const float4*)(Ab + (size_t)(row0 + a_row) * S_ + k0 + a_col4);
        As[a_col4 + 0][a_row] = av.x;
        As[a_col4 + 1][a_row] = av.y;
        As[a_col4 + 2][a_row] = av.z;
        As[a_col4 + 3][a_row] = av.w;
        *(float4*)&Bs[b_row][b_col4] =
            *(const float4*)(Hb + (size_t)(k0 + b_row) * DH + col0 + b_col4);
        __syncthreads();

        #pragma unroll
        for (int kk = 0; kk < BK; kk++) {
            float4 a4 = *(const float4*)&As[kk][ty * 4];
            float4 b4 = *(const float4*)&Bs[kk][tx * 4];
            float ar[4] = {a4.x, a4.y, a4.z, a4.w};
            float br[4] = {b4.x, b4.y, b4.z, b4.w};
            #pragma unroll
            for (int i = 0; i < 4; i++)
                #pragma unroll
                for (int j = 0; j < 4; j++)
                    acc[i][j] = fmaf(ar[i], br[j], acc[i][j]);
        }
        __syncthreads();
    }

    #pragma unroll
    for (int i = 0; i < 4; i++) {
        int r = row0 + ty * 4 + i;
        #pragma unroll
        for (int j = 0; j < 4; j++)
            Cb[(size_t)r * DH + (col0 + tx * 4 + j)] = acc[i][j];
    }
}

// ---------------------------------------------------------------------------
// Head: out = log_softmax(o @ W4 + b4). One warp per row (K=512, N=10).
// ---------------------------------------------------------------------------
__global__ void head_kernel(const float* __restrict__ O, const float* __restrict__ W4,
                            const float* __restrict__ b4, float* __restrict__ out)
{
    __shared__ float w[DH2 * DOUT];         // 20 KB
    const int tid = threadIdx.x;            // 256
    for (int i = tid; i < DH2 * DOUT; i += 256) w[i] = W4[i];
    __syncthreads();

    const int warp = tid >> 5, lane = tid & 31;
    const int row = blockIdx.x * 8 + warp;
    const float* o = O + (size_t)row * DH2;

    float acc[DOUT];
    #pragma unroll
    for (int j = 0; j < DOUT; j++) acc[j] = 0.0f;

    for (int k = lane; k < DH2; k += 32) {
        float ov = o[k];
        const float* wk = &w[k * DOUT];
        #pragma unroll
        for (int j = 0; j < DOUT; j++) acc[j] = fmaf(ov, wk[j], acc[j]);
    }
    #pragma unroll
    for (int j = 0; j < DOUT; j++)
        #pragma unroll
        for (int s = 16; s > 0; s >>= 1)
            acc[j] += __shfl_xor_sync(0xffffffffu, acc[j], s);

    if (lane == 0) {
        float m = -INFINITY;
        #pragma unroll
        for (int j = 0; j < DOUT; j++) { acc[j] += b4[j]; m = fmaxf(m, acc[j]); }
        float sum = 0.0f;
        #pragma unroll
        for (int j = 0; j < DOUT; j++) sum += expf(acc[j] - m);
        float lse = m + logf(sum);
        #pragma unroll
        for (int j = 0; j < DOUT; j++)
            out[(size_t)row * DOUT + j] = acc[j] - lse;
    }
}

// ---------------------------------------------------------------------------
extern "C" void kernel_launch(void* const* d_in, const int* in_sizes, int n_in,
                              void* d_out, int out_size)
{
    const float* input = (const float*)d_in[0];
    const float* gamev = (const float*)d_in[1];
    const float* userv = (const float*)d_in[2];
    const float* W1 = (const float*)d_in[3];
    const float* b1 = (const float*)d_in[4];
    const float* W2 = (const float*)d_in[5];
    const float* b2 = (const float*)d_in[6];
    const float* W3 = (const float*)d_in[7];
    const float* b3 = (const float*)d_in[8];
    const float* W4 = (const float*)d_in[9];
    const float* b4 = (const float*)d_in[10];
    float* out = (float*)d_out;

    float *h1, *h, *attn, *ctx, *o;
    cudaGetSymbolAddress((void**)&h1,   g_h1);
    cudaGetSymbolAddress((void**)&h,    g_h);
    cudaGetSymbolAddress((void**)&attn, g_attn);
    cudaGetSymbolAddress((void**)&ctx,  g_ctx);
    cudaGetSymbolAddress((void**)&o,    g_o);

    // 1) h1 = relu(input @ W1 + b1)   [32768,512]x[512,1024]
    gemm_nn<true><<<dim3((2 * DIN) / 64, M_ / 64), 256>>>(input, W1, b1, h1, M_, 2 * DIN, DIN);
    // 2) h = relu(h1 @ W2 + b2)       [32768,1024]x[1024,1024]
    gemm_nn<true><<<dim3(DH / 64, M_ / 64), 256>>>(h1, W2, b2, h, M_, DH, 2 * DIN);
    // 3) causal scores per batch
    scores_kernel<<<dim3(S_ / 64, S_ / 64, B_), 256>>>(h, attn);
    // 4) causal softmax rows (in place)
    softmax_causal<<<dim3(S_, B_), 256>>>(attn);
    // 5) ctx = attn @ h per batch
    ctx_kernel<<<dim3(DH / 64, S_ / 64, B_), 256>>>(attn, h, ctx);
    // 6) o = relu(ctx @ W3 + b3)      [32768,1024]x[1024,512]
    gemm_nn<true><<<dim3(DH2 / 64, M_ / 64), 256>>>(ctx, W3, b3, o, M_, DH2, DH);
    // 7) out = log_softmax(o @ W4 + b4)
    head_kernel<<<M_ / 8, 256>>>(o, W4, b4, out);

    // 8) pass-through outputs: [out | game_vector | user_vector]
    size_t off = (size_t)M_ * DOUT;
    cudaMemcpyAsync(out + off, gamev, (size_t)in_sizes[1] * sizeof(float),
                    cudaMemcpyDeviceToDevice);
    cudaMemcpyAsync(out + off + in_sizes[1], userv, (size_t)in_sizes[2] * sizeof(float),
                    cudaMemcpyDeviceToDevice);
}

// round 3
// speedup vs baseline: 2.8407x; 2.8407x over previous
#include <cuda_runtime.h>
#include <cstdint>
#include <math.h>

// ---------------- problem constants ----------------
#define B_   16
#define S_   2048
#define DIN  512
#define DH   1024
#define DH2  512
#define DOUT 10
#define M_   (B_ * S_)   // 32768

// ---------------- scratch (device globals; allocation-free) ----------------
__device__ float g_h1 [(size_t)M_ * (2 * DIN)];
__device__ float g_h  [(size_t)M_ * DH];
__device__ float g_attn[(size_t)B_ * S_ * S_];
__device__ float g_ctx[(size_t)M_ * DH];
__device__ float g_o  [(size_t)M_ * DH2];

// ---------------- helpers ----------------
__device__ __forceinline__ uint32_t f2tf32(float f) {
    uint32_t u;
    asm("cvt.rna.tf32.f32 %0, %1;" : "=r"(u) : "f"(f));
    return u;
}

__device__ __forceinline__ void mma_tf32(float* d, const uint32_t* a, const uint32_t* b) {
    asm volatile(
        "mma.sync.aligned.m16n8k8.row.col.f32.tf32.tf32.f32 "
        "{%0,%1,%2,%3}, {%4,%5,%6,%7}, {%8,%9}, {%0,%1,%2,%3};"
        : "+f"(d[0]), "+f"(d[1]), "+f"(d[2]), "+f"(d[3])
        : "r"(a[0]), "r"(a[1]), "r"(a[2]), "r"(a[3]), "r"(b[0]), "r"(b[1]));
}

// XOR swizzle for the [k][128] SMEM operand layout (float offsets).
// Conflict-free for both the transpose fill (4 scalar STS per float4) and
// the mma fragment LDS patterns (verified bank math by construction).
__device__ __forceinline__ int swz(int kk) {
    return (((kk) & 3) ^ (((kk) >> 2) & 3)) << 3;
}
__device__ __forceinline__ int sofs(int kk, int m) {
    return kk * 128 + (m ^ swz(kk));
}

// ---------------------------------------------------------------------------
// tf32 mma.sync GEMM: C[M,N] = act(A[M,K] @ B + bias)
//   A row-major [M,K].
//   BTRANS=false: B row-major [K,N] (weights; H for ctx GEMM).
//   BTRANS=true : B row-major [N,K] (H for scores GEMM: B[n][k]).
// CTA tile 128x128, BK=16, double-buffered SMEM, 8 warps = 2(m) x 4(n),
// warp tile 64x32 = 4x4 m16n8k8 tiles. Batched via blockIdx.z.
// ---------------------------------------------------------------------------
template<bool RELU, bool HAS_BIAS, bool BTRANS, bool CSKIP, bool KCUT>
__global__ void __launch_bounds__(256, 2)
gemm_mma(const float* __restrict__ A, const float* __restrict__ Bsrc,
         const float* __restrict__ bias, float* __restrict__ C,
         int lda, int ldb, int ldc, int K,
         size_t strA, size_t strB, size_t strC)
{
    const int m0 = blockIdx.y * 128;
    const int n0 = blockIdx.x * 128;
    if (CSKIP && n0 > m0 + 127) return;     // tile fully above causal diagonal

    A    += (size_t)blockIdx.z * strA;
    Bsrc += (size_t)blockIdx.z * strB;
    C    += (size_t)blockIdx.z * strC;

    const int Keff = KCUT ? ((m0 + 128) < K ? (m0 + 128) : K) : K;
    const int NC = Keff >> 4;               // BK=16 stages

    __shared__ uint32_t sA[2][16 * 128];
    __shared__ uint32_t sB[2][16 * 128];

    const int tid  = threadIdx.x;
    const int lane = tid & 31;
    const int wid  = tid >> 5;
    const int wm   = wid & 1;               // 0..1 (64 rows each)
    const int wn   = wid >> 1;              // 0..3 (32 cols each)

    float acc[4][4][4];
    #pragma unroll
    for (int i = 0; i < 4; i++)
        #pragma unroll
        for (int j = 0; j < 4; j++)
            #pragma unroll
            for (int r = 0; r < 4; r++) acc[i][j][r] = 0.0f;

    // ---- global prefetch registers ----
    float4 ra[2], rb[2];

    const int a_m  = tid >> 2;              // 0..63
    const int a_kq = tid & 3;               // 0..3 (float4 along k)
    const int b_kk = tid >> 4;              // 0..15 (direct fill)
    const int b_nq = tid & 15;              // 0..15

    #define LDG_A(c) do {                                                         \
        const float* _p = A + (size_t)(m0 + a_m) * lda + (c) * 16 + a_kq * 4;     \
        ra[0] = *(const float4*)_p;                                               \
        ra[1] = *(const float4*)(_p + (size_t)64 * lda);                          \
    } while (0)

    #define LDG_B(c) do {                                                         \
        if (BTRANS) {                                                             \
            const float* _p = Bsrc + (size_t)(n0 + a_m) * ldb + (c) * 16 + a_kq * 4; \
            rb[0] = *(const float4*)_p;                                           \
            rb[1] = *(const float4*)(_p + (size_t)64 * ldb);                      \
        } else {                                                                  \
            const float* _p = Bsrc + (size_t)((c) * 16 + b_kk) * ldb + n0 + b_nq * 4; \
            rb[0] = *(const float4*)_p;                                           \
            rb[1] = *(const float4*)(_p + 64);                                    \
        }                                                                         \
    } while (0)

    #define STS_STAGE(buf) do {                                                   \
        /* A: transpose fill, 4 scalar STS per float4 */                          \
        {                                                                         \
            float v[8] = {ra[0].x, ra[0].y, ra[0].z, ra[0].w,                     \
                          ra[1].x, ra[1].y, ra[1].z, ra[1].w};                    \
            _Pragma("unroll")                                                     \
            for (int h = 0; h < 2; h++) {                                         \
                int mm = a_m + 64 * h;                                            \
                _Pragma("unroll")                                                 \
                for (int j = 0; j < 4; j++)                                       \
                    sA[buf][sofs(a_kq * 4 + j, mm)] = f2tf32(v[h * 4 + j]);       \
            }                                                                     \
        }                                                                         \
        if (BTRANS) {                                                             \
            float v[8] = {rb[0].x, rb[0].y, rb[0].z, rb[0].w,                     \
                          rb[1].x, rb[1].y, rb[1].z, rb[1].w};                    \
            _Pragma("unroll")                                                     \
            for (int h = 0; h < 2; h++) {                                         \
                int nn = a_m + 64 * h;                                            \
                _Pragma("unroll")                                                 \
                for (int j = 0; j < 4; j++)                                       \
                    sB[buf][sofs(a_kq * 4 + j, nn)] = f2tf32(v[h * 4 + j]);       \
            }                                                                     \
        } else {                                                                  \
            _Pragma("unroll")                                                     \
            for (int it = 0; it < 2; it++) {                                      \
                float4 q = rb[it];                                                \
                uint4 u;                                                          \
                u.x = f2tf32(q.x); u.y = f2tf32(q.y);                             \
                u.z = f2tf32(q.z); u.w = f2tf32(q.w);                             \
                int nn = b_nq * 4 + 64 * it;                                      \
                *(uint4*)&sB[buf][sofs(b_kk, nn & ~3) + (0)] = u;                 \
            }                                                                     \
        }                                                                         \
    } while (0)

    // ---- pipeline ----
    LDG_A(0); LDG_B(0);
    STS_STAGE(0);
    __syncthreads();

    const int fc = lane & 3;                // fragment k within 4
    const int fr = lane >> 2;               // fragment row/col within 8

    for (int c = 0; c < NC; ++c) {
        const int cur = c & 1;
        if (c + 1 < NC) { LDG_A(c + 1); LDG_B(c + 1); }

        #pragma unroll
        for (int s = 0; s < 2; ++s) {       // two k8 steps
            const int k0 = 8 * s + fc;
            const int k1 = k0 + 4;
            uint32_t bf[4][2];
            #pragma unroll
            for (int nt = 0; nt < 4; ++nt) {
                int n = wn * 32 + nt * 8 + fr;
                bf[nt][0] = sB[cur][sofs(k0, n)];
                bf[nt][1] = sB[cur][sofs(k1, n)];
            }
            #pragma unroll
            for (int mt = 0; mt < 4; ++mt) {
                int mb = wm * 64 + mt * 16;
                uint32_t af[4];
                af[0] = sA[cur][sofs(k0, mb + fr)];
                af[1] = sA[cur][sofs(k0, mb + fr + 8)];
                af[2] = sA[cur][sofs(k1, mb + fr)];
                af[3] = sA[cur][sofs(k1, mb + fr + 8)];
                #pragma unroll
                for (int nt = 0; nt < 4; ++nt)
                    mma_tf32(acc[mt][nt], af, bf[nt]);
            }
        }

        if (c + 1 < NC) {
            STS_STAGE((c + 1) & 1);
            __syncthreads();
        }
    }

    // ---- epilogue ----
    #pragma unroll
    for (int mt = 0; mt < 4; ++mt) {
        #pragma unroll
        for (int nt = 0; nt < 4; ++nt) {
            int row = m0 + wm * 64 + mt * 16 + fr;
            int col = n0 + wn * 32 + nt * 8 + 2 * fc;
            float b0 = 0.f, b1 = 0.f;
            if (HAS_BIAS) { b0 = bias[col]; b1 = bias[col + 1]; }
            float2 v0, v1;
            v0.x = acc[mt][nt][0] + b0;  v0.y = acc[mt][nt][1] + b1;
            v1.x = acc[mt][nt][2] + b0;  v1.y = acc[mt][nt][3] + b1;
            if (RELU) {
                v0.x = fmaxf(v0.x, 0.f); v0.y = fmaxf(v0.y, 0.f);
                v1.x = fmaxf(v1.x, 0.f); v1.y = fmaxf(v1.y, 0.f);
            }
            *(float2*)(C + (size_t)row * ldc + col) = v0;
            *(float2*)(C + (size_t)(row + 8) * ldc + col) = v1;
        }
    }
    #undef LDG_A
    #undef LDG_B
    #undef STS_STAGE
}

// ---------------------------------------------------------------------------
// Row-wise causal softmax (in place); zeros above the diagonal.
// ---------------------------------------------------------------------------
__global__ void softmax_causal(float* __restrict__ Sc)
{
    const int row = blockIdx.x, bb = blockIdx.y;
    float* r = Sc + (size_t)bb * S_ * S_ + (size_t)row * S_;
    const int n = row + 1;
    const int tid = threadIdx.x;
    __shared__ float red[256];

    float m = -INFINITY;
    for (int j = tid; j < n; j += 256) m = fmaxf(m, r[j]);
    red[tid] = m; __syncthreads();
    for (int s = 128; s > 0; s >>= 1) {
        if (tid < s) red[tid] = fmaxf(red[tid], red[tid + s]);
        __syncthreads();
    }
    m = red[0]; __syncthreads();

    float sum = 0.0f;
    for (int j = tid; j < n; j += 256) sum += __expf(r[j] - m);
    red[tid] = sum; __syncthreads();
    for (int s = 128; s > 0; s >>= 1) {
        if (tid < s) red[tid] += red[tid + s];
        __syncthreads();
    }
    const float inv = 1.0f / red[0];
    for (int j = tid; j < S_; j += 256)
        r[j] = (j < n) ? __expf(r[j] - m) * inv : 0.0f;
}

// ---------------------------------------------------------------------------
// Head: out = log_softmax(o @ W4 + b4). One warp per row (K=512, N=10).
// ---------------------------------------------------------------------------
__global__ void head_kernel(const float* __restrict__ O, const float* __restrict__ W4,
                            const float* __restrict__ b4, float* __restrict__ out)
{
    __shared__ float w[DH2 * DOUT];
    const int tid = threadIdx.x;
    for (int i = tid; i < DH2 * DOUT; i += 256) w[i] = W4[i];
    __syncthreads();

    const int warp = tid >> 5, lane = tid & 31;
    const int row = blockIdx.x * 8 + warp;
    const float* o = O + (size_t)row * DH2;

    float acc[DOUT];
    #pragma unroll
    for (int j = 0; j < DOUT; j++) acc[j] = 0.0f;
    for (int k = lane; k < DH2; k += 32) {
        float ov = o[k];
        const float* wk = &w[k * DOUT];
        #pragma unroll
        for (int j = 0; j < DOUT; j++) acc[j] = fmaf(ov, wk[j], acc[j]);
    }
    #pragma unroll
    for (int j = 0; j < DOUT; j++)
        #pragma unroll
        for (int s = 16; s > 0; s >>= 1)
            acc[j] += __shfl_xor_sync(0xffffffffu, acc[j], s);

    if (lane == 0) {
        float m = -INFINITY;
        #pragma unroll
        for (int j = 0; j < DOUT; j++) { acc[j] += b4[j]; m = fmaxf(m, acc[j]); }
        float sum = 0.0f;
        #pragma unroll
        for (int j = 0; j < DOUT; j++) sum += expf(acc[j] - m);
        float lse = m + logf(sum);
        #pragma unroll
        for (int j = 0; j < DOUT; j++)
            out[(size_t)row * DOUT + j] = acc[j] - lse;
    }
}

// ---------------------------------------------------------------------------
extern "C" void kernel_launch(void* const* d_in, const int* in_sizes, int n_in,
                              void* d_out, int out_size)
{
    const float* input = (const float*)d_in[0];
    const float* gamev = (const float*)d_in[1];
    const float* userv = (const float*)d_in[2];
    const float* W1 = (const float*)d_in[3];
    const float* b1 = (const float*)d_in[4];
    const float* W2 = (const float*)d_in[5];
    const float* b2 = (const float*)d_in[6];
    const float* W3 = (const float*)d_in[7];
    const float* b3 = (const float*)d_in[8];
    const float* W4 = (const float*)d_in[9];
    const float* b4 = (const float*)d_in[10];
    float* out = (float*)d_out;

    float *h1, *h, *attn, *ctx, *o;
    cudaGetSymbolAddress((void**)&h1,   g_h1);
    cudaGetSymbolAddress((void**)&h,    g_h);
    cudaGetSymbolAddress((void**)&attn, g_attn);
    cudaGetSymbolAddress((void**)&ctx,  g_ctx);
    cudaGetSymbolAddress((void**)&o,    g_o);

    // 1) h1 = relu(input @ W1 + b1)    M=32768 N=1024 K=512
    gemm_mma<true, true, false, false, false><<<dim3(8, 256, 1), 256>>>(
        input, W1, b1, h1, DIN, 2 * DIN, 2 * DIN, DIN, 0, 0, 0);
    // 2) h = relu(h1 @ W2 + b2)        M=32768 N=1024 K=1024
    gemm_mma<true, true, false, false, false><<<dim3(8, 256, 1), 256>>>(
        h1, W2, b2, h, 2 * DIN, DH, DH, 2 * DIN, 0, 0, 0);
    // 3) scores = H @ H^T per batch (lower-tri tiles only), B transposed fill
    gemm_mma<false, false, true, true, false><<<dim3(16, 16, B_), 256>>>(
        h, h, nullptr, attn, DH, DH, S_, DH,
        (size_t)S_ * DH, (size_t)S_ * DH, (size_t)S_ * S_);
    // 4) causal softmax in place
    softmax_causal<<<dim3(S_, B_), 256>>>(attn);
    // 5) ctx = attn @ H per batch (K cutoff at m0+128)
    gemm_mma<false, false, false, false, true><<<dim3(8, 16, B_), 256>>>(
        attn, h, nullptr, ctx, S_, DH, DH, S_,
        (size_t)S_ * S_, (size_t)S_ * DH, (size_t)S_ * DH);
    // 6) o = relu(ctx @ W3 + b3)       M=32768 N=512 K=1024
    gemm_mma<true, true, false, false, false><<<dim3(4, 256, 1), 256>>>(
        ctx, W3, b3, o, DH, DH2, DH2, DH, 0, 0, 0);
    // 7) head + log_softmax
    head_kernel<<<M_ / 8, 256>>>(o, W4, b4, out);

    // 8) pass-through
    size_t off = (size_t)M_ * DOUT;
    cudaMemcpyAsync(out + off, gamev, (size_t)in_sizes[1] * sizeof(float),
                    cudaMemcpyDeviceToDevice);
    cudaMemcpyAsync(out + off + in_sizes[1], userv, (size_t)in_sizes[2] * sizeof(float),
                    cudaMemcpyDeviceToDevice);
}

// round 4
// speedup vs baseline: 3.7465x; 1.3189x over previous
#include <cuda_runtime.h>
#include <cstdint>
#include <math.h>

// ---------------- problem constants ----------------
#define B_   16
#define S_   2048
#define DIN  512
#define DH   1024
#define DH2  512
#define DOUT 10
#define M_   (B_ * S_)   // 32768

// ---------------- scratch (device globals; allocation-free) ----------------
__device__ float g_h1 [(size_t)M_ * (2 * DIN)];
__device__ float g_h  [(size_t)M_ * DH];
__device__ float g_attn[(size_t)B_ * S_ * S_];
__device__ float g_ctx[(size_t)M_ * DH];
__device__ float g_o  [(size_t)M_ * DH2];
__device__ float g_inr[(size_t)M_ * DIN];          // tf32-rounded input
__device__ float g_w1r[(size_t)DIN * (2 * DIN)];
__device__ float g_w2r[(size_t)(2 * DIN) * DH];
__device__ float g_w3r[(size_t)DH * DH2];

// ---------------- helpers ----------------
__device__ __forceinline__ uint32_t f2tf32(float f) {
    uint32_t u;
    asm("cvt.rna.tf32.f32 %0, %1;" : "=r"(u) : "f"(f));
    return u;
}
__device__ __forceinline__ float round_tf32(float f) {
    return __uint_as_float(f2tf32(f));
}
__device__ __forceinline__ uint32_t smem_u32(const void* p) {
    uint32_t a;
    asm("{ .reg .u64 t; cvta.to.shared.u64 t, %1; cvt.u32.u64 %0, t; }" : "=r"(a) : "l"(p));
    return a;
}
__device__ __forceinline__ void cp16(uint32_t dst, const void* src) {
    asm volatile("cp.async.cg.shared.global [%0], [%1], 16;" :: "r"(dst), "l"(src));
}
#define CP_COMMIT() asm volatile("cp.async.commit_group;" ::: "memory")
#define CP_WAIT(N)  asm volatile("cp.async.wait_group %0;" :: "n"(N) : "memory")

__device__ __forceinline__ void mma_tf32(float* d, const uint32_t* a, const uint32_t* b) {
    asm volatile(
        "mma.sync.aligned.m16n8k8.row.col.f32.tf32.tf32.f32 "
        "{%0,%1,%2,%3}, {%4,%5,%6,%7}, {%8,%9}, {%0,%1,%2,%3};"
        : "+f"(d[0]), "+f"(d[1]), "+f"(d[2]), "+f"(d[3])
        : "r"(a[0]), "r"(a[1]), "r"(a[2]), "r"(a[3]), "r"(b[0]), "r"(b[1]));
}

// ---------------- GEMM geometry ----------------
// CTA tile 128x128, BK=16, 4-stage cp.async pipeline, 8 warps = 2(m) x 4(n),
// warp tile 64x32 = 4x4 m16n8k8 MMAs per k8 step.
// SMEM per stage: A [128 rows][16k + 4 pad] fp32 = 10240 B
//                 B direct [16k][128n + 8 pad]   =  8704 B (fits in 10240 slot for BTRANS A-style)
#define APITCH 20
#define BPITCH 136
#define ABYTES 10240
#define SBYTES 20480
#define STAGES 4
#define GEMM_SMEM (STAGES * SBYTES)   // 81920

// ---------------------------------------------------------------------------
// tf32 mma.sync GEMM: C[M,N] = act(A[M,K] @ B + bias)
//   A row-major [M,K] (tf32-pre-rounded).
//   BTRANS=false: B row-major [K,N]; BTRANS=true: B row-major [N,K].
// Batched via blockIdx.z.
// ---------------------------------------------------------------------------
template<bool RELU, bool HAS_BIAS, bool BTRANS, bool CSKIP, bool KCUT, bool ROUND>
__global__ void __launch_bounds__(256, 2)
gemm_mma(const float* __restrict__ A, const float* __restrict__ Bsrc,
         const float* __restrict__ bias, float* __restrict__ C,
         int lda, int ldb, int ldc, int K,
         size_t strA, size_t strB, size_t strC)
{
    const int m0 = blockIdx.y * 128;
    const int n0 = blockIdx.x * 128;
    if (CSKIP && n0 > m0 + 127) return;      // tile fully above causal diagonal

    A    += (size_t)blockIdx.z * strA;
    Bsrc += (size_t)blockIdx.z * strB;
    C    += (size_t)blockIdx.z * strC;

    const int Keff = KCUT ? ((m0 + 128) < K ? (m0 + 128) : K) : K;
    const int NC = Keff >> 4;

    extern __shared__ char smem[];
    const uint32_t sb = smem_u32(smem);

    const int tid  = threadIdx.x;
    const int lane = tid & 31;
    const int wid  = tid >> 5;
    const int wm   = wid & 1;
    const int wn   = wid >> 1;
    const int fc   = lane & 3;
    const int fr   = lane >> 2;

    // fill-thread mapping
    const int a_row = tid >> 2, a_q = tid & 3;           // + second half at tid+256
    const int b_row = tid >> 5, b_q = tid & 31;          // B direct

    #define FILL(stage, c) do {                                                    \
        uint32_t _ab = sb + (stage) * SBYTES;                                      \
        uint32_t _bb = _ab + ABYTES;                                               \
        const int _k = (c) * 16;                                                   \
        _Pragma("unroll")                                                          \
        for (int hh = 0; hh < 2; hh++) {                                           \
            int r = a_row + hh * 64;                                               \
            cp16(_ab + (uint32_t)(r * APITCH + a_q * 4) * 4,                       \
                 A + (size_t)(m0 + r) * lda + _k + a_q * 4);                       \
        }                                                                          \
        if (BTRANS) {                                                              \
            _Pragma("unroll")                                                      \
            for (int hh = 0; hh < 2; hh++) {                                       \
                int r = a_row + hh * 64;                                           \
                cp16(_bb + (uint32_t)(r * APITCH + a_q * 4) * 4,                   \
                     Bsrc + (size_t)(n0 + r) * ldb + _k + a_q * 4);                \
            }                                                                      \
        } else {                                                                   \
            _Pragma("unroll")                                                      \
            for (int hh = 0; hh < 2; hh++) {                                       \
                int r = b_row + hh * 8;                                            \
                cp16(_bb + (uint32_t)(r * BPITCH + b_q * 4) * 4,                   \
                     Bsrc + (size_t)(_k + r) * ldb + n0 + b_q * 4);                \
            }                                                                      \
        }                                                                          \
    } while (0)

    float acc[4][4][4];
    #pragma unroll
    for (int i = 0; i < 4; i++)
        #pragma unroll
        for (int j = 0; j < 4; j++)
            #pragma unroll
            for (int r = 0; r < 4; r++) acc[i][j][r] = 0.0f;

    // prologue: stages 0..STAGES-2
    #pragma unroll
    for (int s = 0; s < STAGES - 1; s++) {
        if (s < NC) FILL(s, s);
        CP_COMMIT();
    }

    for (int c = 0; c < NC; ++c) {
        if (c + STAGES - 1 < NC) FILL((c + STAGES - 1) % STAGES, c + STAGES - 1);
        CP_COMMIT();
        CP_WAIT(STAGES - 1);                 // stage c complete (this thread)
        __syncthreads();                     // visible to all warps

        const uint32_t* sAp = (const uint32_t*)(smem + (c % STAGES) * SBYTES);
        const uint32_t* sBp = (const uint32_t*)(smem + (c % STAGES) * SBYTES + ABYTES);

        #pragma unroll
        for (int s = 0; s < 2; ++s) {
            const int k0 = 8 * s + fc;
            const int k1 = k0 + 4;
            uint32_t bf[4][2];
            #pragma unroll
            for (int nt = 0; nt < 4; ++nt) {
                const int n = wn * 32 + nt * 8 + fr;
                if (BTRANS) {
                    bf[nt][0] = sBp[n * APITCH + k0];
                    bf[nt][1] = sBp[n * APITCH + k1];
                } else {
                    bf[nt][0] = sBp[k0 * BPITCH + n];
                    bf[nt][1] = sBp[k1 * BPITCH + n];
                }
            }
            #pragma unroll
            for (int mt = 0; mt < 4; ++mt) {
                const int m = wm * 64 + mt * 16 + fr;
                uint32_t af[4];
                af[0] = sAp[m * APITCH + k0];
                af[1] = sAp[(m + 8) * APITCH + k0];
                af[2] = sAp[m * APITCH + k1];
                af[3] = sAp[(m + 8) * APITCH + k1];
                #pragma unroll
                for (int nt = 0; nt < 4; ++nt)
                    mma_tf32(acc[mt][nt], af, bf[nt]);
            }
        }
        __syncthreads();                     // all reads of stage c done
    }

    // ---- epilogue ----
    #pragma unroll
    for (int mt = 0; mt < 4; ++mt) {
        #pragma unroll
        for (int nt = 0; nt < 4; ++nt) {
            const int row = m0 + wm * 64 + mt * 16 + fr;
            const int col = n0 + wn * 32 + nt * 8 + 2 * fc;
            float b0 = 0.f, b1 = 0.f;
            if (HAS_BIAS) { b0 = bias[col]; b1 = bias[col + 1]; }
            float2 v0, v1;
            v0.x = acc[mt][nt][0] + b0;  v0.y = acc[mt][nt][1] + b1;
            v1.x = acc[mt][nt][2] + b0;  v1.y = acc[mt][nt][3] + b1;
            if (RELU) {
                v0.x = fmaxf(v0.x, 0.f); v0.y = fmaxf(v0.y, 0.f);
                v1.x = fmaxf(v1.x, 0.f); v1.y = fmaxf(v1.y, 0.f);
            }
            if (ROUND) {
                v0.x = round_tf32(v0.x); v0.y = round_tf32(v0.y);
                v1.x = round_tf32(v1.x); v1.y = round_tf32(v1.y);
            }
            *(float2*)(C + (size_t)row * ldc + col) = v0;
            *(float2*)(C + (size_t)(row + 8) * ldc + col) = v1;
        }
    }
    #undef FILL
}

// ---------------------------------------------------------------------------
// Elementwise tf32 rounding (inputs/weights), float4 grid-stride.
// ---------------------------------------------------------------------------
__global__ void round_k(const float* __restrict__ in, float* __restrict__ out, int n4)
{
    int i = blockIdx.x * 256 + threadIdx.x;
    if (i < n4) {
        float4 v = ((const float4*)in)[i];
        v.x = round_tf32(v.x); v.y = round_tf32(v.y);
        v.z = round_tf32(v.z); v.w = round_tf32(v.w);
        ((float4*)out)[i] = v;
    }
}

// ---------------------------------------------------------------------------
// Row-wise causal softmax (in place); zeros above diagonal; tf32-rounds output
// (it feeds the ctx GEMM's A operand).
// ---------------------------------------------------------------------------
__global__ void softmax_causal(float* __restrict__ Sc)
{
    const int row = blockIdx.x, bb = blockIdx.y;
    float* r = Sc + (size_t)bb * S_ * S_ + (size_t)row * S_;
    const int n = row + 1;
    const int tid = threadIdx.x;
    __shared__ float red[256];

    float m = -INFINITY;
    for (int j = tid; j < n; j += 256) m = fmaxf(m, r[j]);
    red[tid] = m; __syncthreads();
    for (int s = 128; s > 0; s >>= 1) {
        if (tid < s) red[tid] = fmaxf(red[tid], red[tid + s]);
        __syncthreads();
    }
    m = red[0]; __syncthreads();

    float sum = 0.0f;
    for (int j = tid; j < n; j += 256) sum += __expf(r[j] - m);
    red[tid] = sum; __syncthreads();
    for (int s = 128; s > 0; s >>= 1) {
        if (tid < s) red[tid] += red[tid + s];
        __syncthreads();
    }
    const float inv = 1.0f / red[0];
    for (int j = tid; j < S_; j += 256)
        r[j] = (j < n) ? round_tf32(__expf(r[j] - m) * inv) : 0.0f;
}

// ---------------------------------------------------------------------------
// Head: out = log_softmax(o @ W4 + b4). One warp per row (K=512, N=10).
// ---------------------------------------------------------------------------
__global__ void head_kernel(const float* __restrict__ O, const float* __restrict__ W4,
                            const float* __restrict__ b4, float* __restrict__ out)
{
    __shared__ float w[DH2 * DOUT];
    const int tid = threadIdx.x;
    for (int i = tid; i < DH2 * DOUT; i += 256) w[i] = W4[i];
    __syncthreads();

    const int warp = tid >> 5, lane = tid & 31;
    const int row = blockIdx.x * 8 + warp;
    const float* o = O + (size_t)row * DH2;

    float acc[DOUT];
    #pragma unroll
    for (int j = 0; j < DOUT; j++) acc[j] = 0.0f;
    for (int k = lane; k < DH2; k += 32) {
        float ov = o[k];
        const float* wk = &w[k * DOUT];
        #pragma unroll
        for (int j = 0; j < DOUT; j++) acc[j] = fmaf(ov, wk[j], acc[j]);
    }
    #pragma unroll
    for (int j = 0; j < DOUT; j++)
        #pragma unroll
        for (int s = 16; s > 0; s >>= 1)
            acc[j] += __shfl_xor_sync(0xffffffffu, acc[j], s);

    if (lane == 0) {
        float m = -INFINITY;
        #pragma unroll
        for (int j = 0; j < DOUT; j++) { acc[j] += b4[j]; m = fmaxf(m, acc[j]); }
        float sum = 0.0f;
        #pragma unroll
        for (int j = 0; j < DOUT; j++) sum += expf(acc[j] - m);
        float lse = m + logf(sum);
        #pragma unroll
        for (int j = 0; j < DOUT; j++)
            out[(size_t)row * DOUT + j] = acc[j] - lse;
    }
}

// ---------------------------------------------------------------------------
extern "C" void kernel_launch(void* const* d_in, const int* in_sizes, int n_in,
                              void* d_out, int out_size)
{
    const float* input = (const float*)d_in[0];
    const float* gamev = (const float*)d_in[1];
    const float* userv = (const float*)d_in[2];
    const float* W1 = (const float*)d_in[3];
    const float* b1 = (const float*)d_in[4];
    const float* W2 = (const float*)d_in[5];
    const float* b2 = (const float*)d_in[6];
    const float* W3 = (const float*)d_in[7];
    const float* b3 = (const float*)d_in[8];
    const float* W4 = (const float*)d_in[9];
    const float* b4 = (const float*)d_in[10];
    float* out = (float*)d_out;

    float *h1, *h, *attn, *ctx, *o, *inr, *w1r, *w2r, *w3r;
    cudaGetSymbolAddress((void**)&h1,   g_h1);
    cudaGetSymbolAddress((void**)&h,    g_h);
    cudaGetSymbolAddress((void**)&attn, g_attn);
    cudaGetSymbolAddress((void**)&ctx,  g_ctx);
    cudaGetSymbolAddress((void**)&o,    g_o);
    cudaGetSymbolAddress((void**)&inr,  g_inr);
    cudaGetSymbolAddress((void**)&w1r,  g_w1r);
    cudaGetSymbolAddress((void**)&w2r,  g_w2r);
    cudaGetSymbolAddress((void**)&w3r,  g_w3r);

    auto g_mlpR = gemm_mma<true,  true,  false, false, false, true >;  // relu+bias, round out
    auto g_sc   = gemm_mma<false, false, true,  true,  false, false>;  // scores
    auto g_ctxk = gemm_mma<false, false, false, false, true,  true >;  // ctx, round out
    auto g_mlpN = gemm_mma<true,  true,  false, false, false, false>;  // final mlp, raw out
    cudaFuncSetAttribute(g_mlpR, cudaFuncAttributeMaxDynamicSharedMemorySize, GEMM_SMEM);
    cudaFuncSetAttribute(g_sc,   cudaFuncAttributeMaxDynamicSharedMemorySize, GEMM_SMEM);
    cudaFuncSetAttribute(g_ctxk, cudaFuncAttributeMaxDynamicSharedMemorySize, GEMM_SMEM);
    cudaFuncSetAttribute(g_mlpN, cudaFuncAttributeMaxDynamicSharedMemorySize, GEMM_SMEM);

    // Pre-round mma inputs to tf32 (rna)
    round_k<<<(M_ * DIN / 4 + 255) / 256, 256>>>(input, inr, M_ * DIN / 4);
    round_k<<<(DIN * 2 * DIN / 4 + 255) / 256, 256>>>(W1, w1r, DIN * 2 * DIN / 4);
    round_k<<<(2 * DIN * DH / 4 + 255) / 256, 256>>>(W2, w2r, 2 * DIN * DH / 4);
    round_k<<<(DH * DH2 / 4 + 255) / 256, 256>>>(W3, w3r, DH * DH2 / 4);

    // 1) h1 = relu(inr @ W1 + b1)    M=32768 N=1024 K=512
    g_mlpR<<<dim3(8, 256, 1), 256, GEMM_SMEM>>>(inr, w1r, b1, h1,
        DIN, 2 * DIN, 2 * DIN, DIN, 0, 0, 0);
    // 2) h = relu(h1 @ W2 + b2)      M=32768 N=1024 K=1024
    g_mlpR<<<dim3(8, 256, 1), 256, GEMM_SMEM>>>(h1, w2r, b2, h,
        2 * DIN, DH, DH, 2 * DIN, 0, 0, 0);
    // 3) scores = H @ H^T per batch (lower-tri tiles only)
    g_sc<<<dim3(16, 16, B_), 256, GEMM_SMEM>>>(h, h, nullptr, attn,
        DH, DH, S_, DH, (size_t)S_ * DH, (size_t)S_ * DH, (size_t)S_ * S_);
    // 4) causal softmax in place (rounds output)
    softmax_causal<<<dim3(S_, B_), 256>>>(attn);
    // 5) ctx = attn @ H per batch (K cutoff at m0+128)
    g_ctxk<<<dim3(8, 16, B_), 256, GEMM_SMEM>>>(attn, h, nullptr, ctx,
        S_, DH, DH, S_, (size_t)S_ * S_, (size_t)S_ * DH, (size_t)S_ * DH);
    // 6) o = relu(ctx @ W3 + b3)     M=32768 N=512 K=1024
    g_mlpN<<<dim3(4, 256, 1), 256, GEMM_SMEM>>>(ctx, w3r, b3, o,
        DH, DH2, DH2, DH, 0, 0, 0);
    // 7) head + log_softmax
    head_kernel<<<M_ / 8, 256>>>(o, W4, b4, out);

    // 8) pass-through
    size_t off = (size_t)M_ * DOUT;
    cudaMemcpyAsync(out + off, gamev, (size_t)in_sizes[1] * sizeof(float),
                    cudaMemcpyDeviceToDevice);
    cudaMemcpyAsync(out + off + in_sizes[1], userv, (size_t)in_sizes[2] * sizeof(float),
                    cudaMemcpyDeviceToDevice);
}